// round 11
// baseline (speedup 1.0000x reference)
#include <cuda_runtime.h>
#include <cuda_bf16.h>
#include <cstdint>

#define B_ROWS 16384
#define L_COLS 1024
#define ROWS_PER_BLK 8
#define NBLKS (B_ROWS / ROWS_PER_BLK)   // 2048
#define NTHR 256
#define STAGES 4

// Per-block partial sums of row losses (no device allocation allowed).
__device__ float g_partials[NBLKS];

__device__ __forceinline__ void cp_async16(uint32_t saddr, const void* gptr) {
    asm volatile("cp.async.cg.shared.global [%0], [%1], 16;"
                 :: "r"(saddr), "l"(gptr) : "memory");
}
__device__ __forceinline__ void cp_commit() {
    asm volatile("cp.async.commit_group;" ::: "memory");
}
template <int N>
__device__ __forceinline__ void cp_wait() {
    asm volatile("cp.async.wait_group %0;" :: "n"(N) : "memory");
}

// 2048 blocks x 256 threads (8 warps). Warp w handles row blockIdx.x*8 + w.
// Per-THREAD cp.async pipeline, STAGES=4 deep: in-flight data lives in smem,
// not registers, so memory-level parallelism is 4x2 LDGSTS per thread with no
// register pressure and no barriers (each thread reads only its own slot).
__global__ void __launch_bounds__(NTHR)
bpmll_row_kernel(const float* __restrict__ c, const int* __restrict__ y,
                 float* __restrict__ partials) {
    __shared__ float4 c_s[STAGES][NTHR];
    __shared__ int4   y_s[STAGES][NTHR];

    const int t = threadIdx.x;
    const int warp = t >> 5;
    const int lane = t & 31;
    const int row = blockIdx.x * ROWS_PER_BLK + warp;

    const float4* __restrict__ c4 =
        reinterpret_cast<const float4*>(c + (size_t)row * L_COLS);
    const int4* __restrict__ y4 =
        reinterpret_cast<const int4*>(y + (size_t)row * L_COLS);

    // Prologue: issue copies for iterations 0..STAGES-2 (one group each).
    #pragma unroll
    for (int i = 0; i < STAGES - 1; i++) {
        cp_async16((uint32_t)__cvta_generic_to_shared(&c_s[i][t]),
                   c4 + i * 32 + lane);
        cp_async16((uint32_t)__cvta_generic_to_shared(&y_s[i][t]),
                   y4 + i * 32 + lane);
        cp_commit();
    }

    float pos = 0.0f, neg = 0.0f;
    int yc = 0;

    #pragma unroll
    for (int i = 0; i < 8; i++) {
        // Guarantee iteration i's group has completed (<= STAGES-2 pending).
        cp_wait<STAGES - 2>();

        const int s = i & (STAGES - 1);
        const float4 cv = c_s[s][t];
        const int4 yv = y_s[s][t];

        // Issue iteration i+STAGES-1's copy into the slot just freed.
        // Always commit (possibly empty group) to keep pending-count uniform.
        const int j = i + STAGES - 1;
        if (j < 8) {
            const int sj = j & (STAGES - 1);
            cp_async16((uint32_t)__cvta_generic_to_shared(&c_s[sj][t]),
                       c4 + j * 32 + lane);
            cp_async16((uint32_t)__cvta_generic_to_shared(&y_s[sj][t]),
                       y4 + j * 32 + lane);
        }
        cp_commit();

        {
            const float e = __expf(__int_as_float(
                __float_as_int(cv.x) ^ (yv.x << 31)));
            if (yv.x) { pos += e; yc++; } else { neg += e; }
        }
        {
            const float e = __expf(__int_as_float(
                __float_as_int(cv.y) ^ (yv.y << 31)));
            if (yv.y) { pos += e; yc++; } else { neg += e; }
        }
        {
            const float e = __expf(__int_as_float(
                __float_as_int(cv.z) ^ (yv.z << 31)));
            if (yv.z) { pos += e; yc++; } else { neg += e; }
        }
        {
            const float e = __expf(__int_as_float(
                __float_as_int(cv.w) ^ (yv.w << 31)));
            if (yv.w) { pos += e; yc++; } else { neg += e; }
        }
    }

    // Warp tree reduction (deterministic).
    #pragma unroll
    for (int off = 16; off > 0; off >>= 1) {
        pos += __shfl_down_sync(0xFFFFFFFFu, pos, off);
        neg += __shfl_down_sync(0xFFFFFFFFu, neg, off);
        yc  += __shfl_down_sync(0xFFFFFFFFu, yc, off);
    }

    __shared__ float s_loss[ROWS_PER_BLK];
    if (lane == 0) {
        const float yn = (float)yc;
        const float ybn = (float)(L_COLS - yc);
        s_loss[warp] = (pos * neg) / (yn * ybn);
    }
    __syncthreads();

    if (t == 0) {
        float sum = 0.0f;
        #pragma unroll
        for (int w = 0; w < ROWS_PER_BLK; w++) sum += s_loss[w];
        partials[blockIdx.x] = sum;
    }
    cudaTriggerProgrammaticLaunchCompletion();
}

// Single-block reduction of 2048 partials -> mean over 16384 rows.
// Launched with PDL; waits on the primary grid before reading partials.
__global__ void __launch_bounds__(512)
bpmll_reduce_kernel(const float* __restrict__ partials, float* __restrict__ out) {
    cudaGridDependencySynchronize();

    const int t = threadIdx.x;
    const float4 v = reinterpret_cast<const float4*>(partials)[t];  // 512*4 = 2048
    float s = (v.x + v.y) + (v.z + v.w);

    #pragma unroll
    for (int off = 16; off > 0; off >>= 1)
        s += __shfl_down_sync(0xFFFFFFFFu, s, off);

    __shared__ float s_w[16];
    const int warp = t >> 5;
    const int lane = t & 31;
    if (lane == 0) s_w[warp] = s;
    __syncthreads();

    if (t == 0) {
        float tot = 0.0f;
        #pragma unroll
        for (int w = 0; w < 16; w++) tot += s_w[w];
        out[0] = tot * (1.0f / (float)B_ROWS);
    }
}

extern "C" void kernel_launch(void* const* d_in, const int* in_sizes, int n_in,
                              void* d_out, int out_size) {
    const float* c = (const float*)d_in[0];
    const int* y = (const int*)d_in[1];
    float* out = (float*)d_out;

    float* partials = nullptr;
    cudaGetSymbolAddress((void**)&partials, g_partials);

    bpmll_row_kernel<<<NBLKS, NTHR>>>(c, y, partials);

    cudaLaunchConfig_t cfg = {};
    cfg.gridDim = dim3(1, 1, 1);
    cfg.blockDim = dim3(512, 1, 1);
    cfg.dynamicSmemBytes = 0;
    cfg.stream = 0;
    cudaLaunchAttribute attrs[1];
    attrs[0].id = cudaLaunchAttributeProgrammaticStreamSerialization;
    attrs[0].val.programmaticStreamSerializationAllowed = 1;
    cfg.attrs = attrs;
    cfg.numAttrs = 1;
    cudaLaunchKernelEx(&cfg, bpmll_reduce_kernel,
                       (const float*)partials, out);
}